// round 16
// baseline (speedup 1.0000x reference)
#include <cuda_runtime.h>
#include <cuda_bf16.h>
#include <math.h>
typedef unsigned int u32;

#define EPSF 1e-6f
#define Bn 16
#define Cn 512
#define Nn 4096
#define Kn 64
#define NUM_STAGES 3
#define NCHUNK 8
#define PSZ (Bn * Cn * Kn)

// device scratch (no allocs allowed)
__device__ u32   g_fw[(size_t)Bn * Cn * Nn];   // packed feats words   128 MB
__device__ u32   g_bw[PSZ];                    // packed bases words     2 MB
__device__ u32   g_attw[(size_t)Bn * Nn * Kn]; // packed att [b][n][k]  16 MB
__device__ u32   g_attT[(size_t)Bn * Kn * Nn]; // packed att [b][k][n]  16 MB
__device__ float g_part[NCHUNK][PSZ];          // bnew partials         16 MB
__device__ float g_bnew[PSZ];
__device__ float g_colsum[Bn * Kn];

// word = (h = bf16(x)) | (l = bf16(x-h)) << 16 ; h+l == x to ~2^-18
__device__ __forceinline__ u32 pack_hl(float x) {
    __nv_bfloat16 h = __float2bfloat16(x);
    __nv_bfloat16 l = __float2bfloat16(x - __bfloat162float(h));
    return (u32)__bfloat16_as_ushort(h) | ((u32)__bfloat16_as_ushort(l) << 16);
}
__device__ __forceinline__ u32 swap16(u32 x) { return __byte_perm(x, x, 0x1032); }
__device__ __forceinline__ void mma_bf16(float* d, const u32* a, u32 b0, u32 b1) {
    asm volatile(
        "mma.sync.aligned.m16n8k16.row.col.f32.bf16.bf16.f32 "
        "{%0,%1,%2,%3},{%4,%5,%6,%7},{%8,%9},{%0,%1,%2,%3};"
        : "+f"(d[0]), "+f"(d[1]), "+f"(d[2]), "+f"(d[3])
        : "r"(a[0]), "r"(a[1]), "r"(a[2]), "r"(a[3]), "r"(b0), "r"(b1));
}

// ---------------------------------------------------------------------------
__global__ void k_pack(const float* __restrict__ f) {
    size_t i = ((size_t)blockIdx.x * 256 + threadIdx.x) * 4;
    float4 v = *(const float4*)(f + i);
    uint4 wv = make_uint4(pack_hl(v.x), pack_hl(v.y), pack_hl(v.z), pack_hl(v.w));
    *(uint4*)&g_fw[i] = wv;
}

// l2-normalize bases over C, broadcast to batches, store packed words
__global__ void k_init(const float* __restrict__ bases) {
    int k = blockIdx.x, tid = threadIdx.x;
    float s = 0.f;
    for (int c = tid; c < Cn; c += 128) {
        float v = bases[c * Kn + k];
        s += v * v;
    }
    __shared__ float sh[128];
    sh[tid] = s;
    __syncthreads();
    for (int o = 64; o > 0; o >>= 1) {
        if (tid < o) sh[tid] += sh[tid + o];
        __syncthreads();
    }
    float inv = 1.f / (EPSF + sqrtf(sh[0]));
    for (int c = tid; c < Cn; c += 128) {
        u32 wv = pack_hl(bases[c * Kn + k] * inv);
        for (int b = 0; b < Bn; b++) g_bw[(b * Cn + c) * Kn + k] = wv;
    }
}

__global__ void k_zero_cs() {
    int i = threadIdx.x;
    if (i < Bn * Kn) g_colsum[i] = 0.f;
}

// ---------------------------------------------------------------------------
// att[n,k] = softmax_k( sum_c f[c,n]*b[c,k] ); packed words out + colsum.
// grid (Nn/128, Bn), 128 thr (4 warps, 5 CTAs/SM); warp = 32n x 64k; 32-c chunks.
__global__ __launch_bounds__(128, 5) void k_att(int storeT) {
    int b = blockIdx.y, n0 = blockIdx.x * 128;
    int tid = threadIdx.x, lane = tid & 31, w = tid >> 5;
    int q = lane & 3, g = lane >> 2;

    __shared__ u32 sA[32][136];   // [c-word][n], pad 8 -> cf fragment reads
    __shared__ u32 sB[32][72];    // [c-word][k]
    __shared__ float colsh[Kn];

    float acc[2][8][4];
#pragma unroll
    for (int mt = 0; mt < 2; mt++)
#pragma unroll
        for (int j = 0; j < 8; j++)
#pragma unroll
            for (int i = 0; i < 4; i++) acc[mt][j][i] = 0.f;

    const u32* fw = g_fw + (size_t)b * Cn * Nn;
    const u32* bw = g_bw + (size_t)b * Cn * Kn;

    for (int c0 = 0; c0 < Cn; c0 += 32) {
#pragma unroll
        for (int t = 0; t < 8; t++) {      // stage A: 32 c-words x 128 n
            int idx = tid + t * 128;       // 0..1023
            int c = idx >> 5, nq = idx & 31;
            *(uint4*)&sA[c][nq * 4] =
                *(const uint4*)&fw[(size_t)(c0 + c) * Nn + n0 + nq * 4];
        }
#pragma unroll
        for (int t = 0; t < 4; t++) {      // stage B: 32 c-words x 64 k
            int idx = tid + t * 128;       // 0..511
            int c = idx >> 4, kq = idx & 15;
            *(uint4*)&sB[c][kq * 4] = *(const uint4*)&bw[(c0 + c) * Kn + kq * 4];
        }
        __syncthreads();
#pragma unroll
        for (int ch = 0; ch < 4; ch++) {
            u32 a[2][4];
#pragma unroll
            for (int mt = 0; mt < 2; mt++) {
                int m = 32 * w + 16 * mt + g;
                a[mt][0] = sA[8 * ch + q][m];
                a[mt][1] = sA[8 * ch + q][m + 8];
                a[mt][2] = sA[8 * ch + q + 4][m];
                a[mt][3] = sA[8 * ch + q + 4][m + 8];
            }
#pragma unroll
            for (int fj = 0; fj < 8; fj++) {
                u32 b0 = sB[8 * ch + q][8 * fj + g];
                u32 b1 = sB[8 * ch + q + 4][8 * fj + g];
                u32 b0s = swap16(b0), b1s = swap16(b1);
                mma_bf16(acc[0][fj], a[0], b0, b1);
                mma_bf16(acc[0][fj], a[0], b0s, b1s);
                mma_bf16(acc[1][fj], a[1], b0, b1);
                mma_bf16(acc[1][fj], a[1], b0s, b1s);
            }
        }
        __syncthreads();
    }

    if (tid < Kn) colsh[tid] = 0.f;

    u32* attb = g_attw + (size_t)b * Nn * Kn;
    u32* aTb = g_attT + (size_t)b * Kn * Nn;
    float cacc0[8], cacc1[8];
#pragma unroll
    for (int fj = 0; fj < 8; fj++) { cacc0[fj] = 0.f; cacc1[fj] = 0.f; }

#pragma unroll
    for (int mt = 0; mt < 2; mt++) {
        float m0 = -1e30f, m1 = -1e30f;
#pragma unroll
        for (int fj = 0; fj < 8; fj++) {
            m0 = fmaxf(m0, fmaxf(acc[mt][fj][0], acc[mt][fj][1]));
            m1 = fmaxf(m1, fmaxf(acc[mt][fj][2], acc[mt][fj][3]));
        }
        m0 = fmaxf(m0, __shfl_xor_sync(0xffffffffu, m0, 1));
        m0 = fmaxf(m0, __shfl_xor_sync(0xffffffffu, m0, 2));
        m1 = fmaxf(m1, __shfl_xor_sync(0xffffffffu, m1, 1));
        m1 = fmaxf(m1, __shfl_xor_sync(0xffffffffu, m1, 2));
        float s0 = 0.f, s1 = 0.f;
#pragma unroll
        for (int fj = 0; fj < 8; fj++) {
            acc[mt][fj][0] = __expf(acc[mt][fj][0] - m0);
            acc[mt][fj][1] = __expf(acc[mt][fj][1] - m0);
            acc[mt][fj][2] = __expf(acc[mt][fj][2] - m1);
            acc[mt][fj][3] = __expf(acc[mt][fj][3] - m1);
            s0 += acc[mt][fj][0] + acc[mt][fj][1];
            s1 += acc[mt][fj][2] + acc[mt][fj][3];
        }
        s0 += __shfl_xor_sync(0xffffffffu, s0, 1);
        s0 += __shfl_xor_sync(0xffffffffu, s0, 2);
        s1 += __shfl_xor_sync(0xffffffffu, s1, 1);
        s1 += __shfl_xor_sync(0xffffffffu, s1, 2);
        float i0 = 1.f / s0, i1 = 1.f / s1;

        int r = n0 + 32 * w + 16 * mt + g;
#pragma unroll
        for (int fj = 0; fj < 8; fj++) {
            float v0 = acc[mt][fj][0] * i0, v1 = acc[mt][fj][1] * i0;
            float v2 = acc[mt][fj][2] * i1, v3 = acc[mt][fj][3] * i1;
            int k0 = 8 * fj + 2 * q;
            *(uint2*)&attb[(size_t)r * Kn + k0] = make_uint2(pack_hl(v0), pack_hl(v1));
            *(uint2*)&attb[(size_t)(r + 8) * Kn + k0] = make_uint2(pack_hl(v2), pack_hl(v3));
            if (storeT) {
                aTb[(size_t)k0 * Nn + r] = pack_hl(v0);
                aTb[(size_t)(k0 + 1) * Nn + r] = pack_hl(v1);
                aTb[(size_t)k0 * Nn + r + 8] = pack_hl(v2);
                aTb[(size_t)(k0 + 1) * Nn + r + 8] = pack_hl(v3);
            }
            cacc0[fj] += v0 + v2;
            cacc1[fj] += v1 + v3;
        }
    }
    __syncthreads();   // colsh zeroed
#pragma unroll
    for (int fj = 0; fj < 8; fj++) {
#pragma unroll
        for (int s = 4; s < 32; s <<= 1) {
            cacc0[fj] += __shfl_xor_sync(0xffffffffu, cacc0[fj], s);
            cacc1[fj] += __shfl_xor_sync(0xffffffffu, cacc1[fj], s);
        }
        if (lane < 4) {
            atomicAdd(&colsh[8 * fj + 2 * q], cacc0[fj]);
            atomicAdd(&colsh[8 * fj + 2 * q + 1], cacc1[fj]);
        }
    }
    __syncthreads();
    if (tid < Kn) atomicAdd(&g_colsum[b * Kn + tid], colsh[tid]);
}

// ---------------------------------------------------------------------------
// part[c,k] = sum_{n in chunk} f[c,n]*att[n,k]
// grid (Cn/128, NCHUNK, Bn), 128 thr (4 warps, 5 CTAs/SM); warp = 32c x 64k.
__global__ __launch_bounds__(128, 5) void k_bnew() {
    int b = blockIdx.z, chunk = blockIdx.y, ct = blockIdx.x * 128;
    int tid = threadIdx.x, lane = tid & 31, w = tid >> 5;
    int q = lane & 3, g = lane >> 2;

    __shared__ u32 sA[128][36];   // [c][n-word]
    __shared__ u32 sB[32][72];    // [n-word][k]

    float acc[2][8][4];
#pragma unroll
    for (int mt = 0; mt < 2; mt++)
#pragma unroll
        for (int j = 0; j < 8; j++)
#pragma unroll
            for (int i = 0; i < 4; i++) acc[mt][j][i] = 0.f;

    const u32* fw = g_fw + (size_t)b * Cn * Nn + (size_t)ct * Nn;
    const u32* aw = g_attw + (size_t)b * Nn * Kn;
    int nb0 = chunk * (Nn / NCHUNK), nb1 = nb0 + Nn / NCHUNK;

    for (int nb = nb0; nb < nb1; nb += 32) {
#pragma unroll
        for (int t = 0; t < 8; t++) {      // stage A: 128 c x 32 n-words
            int idx = tid + t * 128;       // 0..1023
            int c = idx >> 3, nq = idx & 7;
            *(uint4*)&sA[c][nq * 4] = *(const uint4*)&fw[(size_t)c * Nn + nb + nq * 4];
        }
#pragma unroll
        for (int t = 0; t < 4; t++) {      // stage B: 32 n-words x 64 k
            int idx = tid + t * 128;
            int nn = idx >> 4, kq = idx & 15;
            *(uint4*)&sB[nn][kq * 4] =
                *(const uint4*)&aw[(size_t)(nb + nn) * Kn + kq * 4];
        }
        __syncthreads();
#pragma unroll
        for (int ch = 0; ch < 4; ch++) {
            u32 a[2][4];
#pragma unroll
            for (int mt = 0; mt < 2; mt++) {
                int m = 32 * w + 16 * mt + g;
                a[mt][0] = sA[m][8 * ch + q];
                a[mt][1] = sA[m + 8][8 * ch + q];
                a[mt][2] = sA[m][8 * ch + q + 4];
                a[mt][3] = sA[m + 8][8 * ch + q + 4];
            }
#pragma unroll
            for (int fj = 0; fj < 8; fj++) {
                u32 b0 = sB[8 * ch + q][8 * fj + g];
                u32 b1 = sB[8 * ch + q + 4][8 * fj + g];
                u32 b0s = swap16(b0), b1s = swap16(b1);
                mma_bf16(acc[0][fj], a[0], b0, b1);
                mma_bf16(acc[0][fj], a[0], b0s, b1s);
                mma_bf16(acc[1][fj], a[1], b0, b1);
                mma_bf16(acc[1][fj], a[1], b0s, b1s);
            }
        }
        __syncthreads();
    }

    float* pb = g_part[chunk] + (size_t)(b * Cn + ct) * Kn;
#pragma unroll
    for (int mt = 0; mt < 2; mt++) {
        int c = 32 * w + 16 * mt + g;
#pragma unroll
        for (int fj = 0; fj < 8; fj++) {
            int k0 = 8 * fj + 2 * q;
            *(float2*)&pb[(size_t)c * Kn + k0] =
                make_float2(acc[mt][fj][0], acc[mt][fj][1]);
            *(float2*)&pb[(size_t)(c + 8) * Kn + k0] =
                make_float2(acc[mt][fj][2], acc[mt][fj][3]);
        }
    }
}

// ---------------------------------------------------------------------------
__global__ void k_sum() {
    int i = blockIdx.x * 256 + threadIdx.x;
    float s = 0.f;
#pragma unroll
    for (int ch = 0; ch < NCHUNK; ch++) s += g_part[ch][i];
    g_bnew[i] = s;
}

// fused l1(via colsum)+l2 norm; writes packed base words; rezeroes colsum
__global__ void k_bnorm() {
    int blk = blockIdx.x, b = blk >> 6, k = blk & 63, tid = threadIdx.x;
    const float* src = g_bnew + (b * Cn) * Kn + k;
    float v[4], s = 0.f;
#pragma unroll
    for (int i = 0; i < 4; i++) {
        v[i] = src[(tid + i * 128) * Kn];
        s += v[i] * v[i];
    }
    __shared__ float sh[128];
    sh[tid] = s;
    __syncthreads();
    for (int o = 64; o > 0; o >>= 1) {
        if (tid < o) sh[tid] += sh[tid + o];
        __syncthreads();
    }
    float cs = g_colsum[b * Kn + k];
    float inv = 1.f / ((EPSF + cs) * EPSF + sqrtf(sh[0]));
    u32* dst = g_bw + (b * Cn) * Kn + k;
#pragma unroll
    for (int i = 0; i < 4; i++) dst[(tid + i * 128) * Kn] = pack_hl(v[i] * inv);
    __syncthreads();
    if (tid == 0) g_colsum[b * Kn + k] = 0.f;   // ready for next stage
}

// ---------------------------------------------------------------------------
// out[c,n] = sum_k b[c,k]*att[n,k]; A = b words (SMEM), B = attT staged SMEM.
// grid (Nn/64, Cn/128, Bn), 256 thr; warp = 16c x 64n.
__global__ __launch_bounds__(256) void k_recon(float* __restrict__ out) {
    int b = blockIdx.z, ct = blockIdx.y * 128, n0 = blockIdx.x * 64;
    int tid = threadIdx.x, lane = tid & 31, w = tid >> 5;
    int q = lane & 3, g = lane >> 2;

    __shared__ u32 sA[128][68];   // [c][k-word]
    __shared__ u32 sB[32][72];    // [k-word][n]

    const u32* bw = g_bw + (size_t)(b * Cn + ct) * Kn;
#pragma unroll
    for (int t = 0; t < 8; t++) {
        int idx = tid + t * 256;
        int c = idx >> 4, kq = idx & 15;
        *(uint4*)&sA[c][kq * 4] = *(const uint4*)&bw[(size_t)c * Kn + kq * 4];
    }

    const u32* at = g_attT + (size_t)b * Kn * Nn + n0;
    float acc[8][4];
#pragma unroll
    for (int j = 0; j < 8; j++)
#pragma unroll
        for (int i = 0; i < 4; i++) acc[j][i] = 0.f;

#pragma unroll
    for (int half = 0; half < 2; half++) {
        __syncthreads();
#pragma unroll
        for (int t = 0; t < 2; t++) {
            int idx = tid + t * 256;
            int kw = idx >> 4, nq = idx & 15;
            *(uint4*)&sB[kw][nq * 4] =
                *(const uint4*)&at[(size_t)(32 * half + kw) * Nn + nq * 4];
        }
        __syncthreads();
#pragma unroll
        for (int chl = 0; chl < 4; chl++) {
            int colb = 32 * half + 8 * chl;
            u32 a[4];
            a[0] = sA[16 * w + g][colb + q];
            a[1] = sA[16 * w + g + 8][colb + q];
            a[2] = sA[16 * w + g][colb + q + 4];
            a[3] = sA[16 * w + g + 8][colb + q + 4];
#pragma unroll
            for (int fj = 0; fj < 8; fj++) {
                u32 b0 = sB[8 * chl + q][8 * fj + g];
                u32 b1 = sB[8 * chl + q + 4][8 * fj + g];
                mma_bf16(acc[fj], a, b0, b1);
                mma_bf16(acc[fj], a, swap16(b0), swap16(b1));
            }
        }
    }

    float* ob = out + (size_t)(b * Cn + ct) * Nn + n0;
    int c = 16 * w + g;
#pragma unroll
    for (int fj = 0; fj < 8; fj++) {
        int n = 8 * fj + 2 * q;
        *(float2*)&ob[(size_t)c * Nn + n] = make_float2(acc[fj][0], acc[fj][1]);
        *(float2*)&ob[(size_t)(c + 8) * Nn + n] = make_float2(acc[fj][2], acc[fj][3]);
    }
}

// ---------------------------------------------------------------------------
extern "C" void kernel_launch(void* const* d_in, const int* in_sizes, int n_in,
                              void* d_out, int out_size) {
    const float* feats = (const float*)d_in[0];
    const float* bases = (const float*)d_in[1];
    float* out = (float*)d_out;
    (void)in_sizes; (void)n_in; (void)out_size;

    k_pack<<<(int)(((size_t)Bn * Cn * Nn / 4) / 256), 256>>>(feats);
    k_init<<<Kn, 128>>>(bases);
    k_zero_cs<<<1, 1024>>>();

    for (int s = 0; s < NUM_STAGES; s++) {
        k_att<<<dim3(Nn / 128, Bn), 128>>>(s == NUM_STAGES - 1 ? 1 : 0);
        k_bnew<<<dim3(Cn / 128, NCHUNK, Bn), 128>>>();
        k_sum<<<PSZ / 256, 256>>>();
        k_bnorm<<<Bn * Kn, 128>>>();
    }
    k_recon<<<dim3(Nn / 64, Cn / 128, Bn), 256>>>(out);
}

// round 17
// speedup vs baseline: 1.2691x; 1.2691x over previous
#include <cuda_runtime.h>
#include <cuda_bf16.h>
#include <math.h>
typedef unsigned int u32;

#define EPSF 1e-6f
#define Bn 16
#define Cn 512
#define Nn 4096
#define Kn 64
#define NUM_STAGES 3
#define NCHUNK 8
#define PSZ (Bn * Cn * Kn)

// device scratch (no allocs allowed)
__device__ u32   g_fw[(size_t)Bn * Cn * Nn];   // packed feats words   128 MB
__device__ u32   g_bw[PSZ];                    // packed bases words     2 MB
__device__ u32   g_attw[(size_t)Bn * Nn * Kn]; // packed att [b][n][k]  16 MB
__device__ float g_part[NCHUNK][PSZ];          // bnew partials         16 MB
__device__ float g_bnew[PSZ];
__device__ float g_colsum[Bn * Kn];

// word = (h = bf16(x)) | (l = bf16(x-h)) << 16 ; h+l == x to ~2^-18
__device__ __forceinline__ u32 pack_hl(float x) {
    __nv_bfloat16 h = __float2bfloat16(x);
    __nv_bfloat16 l = __float2bfloat16(x - __bfloat162float(h));
    return (u32)__bfloat16_as_ushort(h) | ((u32)__bfloat16_as_ushort(l) << 16);
}
__device__ __forceinline__ u32 swap16(u32 x) { return __byte_perm(x, x, 0x1032); }
__device__ __forceinline__ void mma_bf16(float* d, const u32* a, u32 b0, u32 b1) {
    asm volatile(
        "mma.sync.aligned.m16n8k16.row.col.f32.bf16.bf16.f32 "
        "{%0,%1,%2,%3},{%4,%5,%6,%7},{%8,%9},{%0,%1,%2,%3};"
        : "+f"(d[0]), "+f"(d[1]), "+f"(d[2]), "+f"(d[3])
        : "r"(a[0]), "r"(a[1]), "r"(a[2]), "r"(a[3]), "r"(b0), "r"(b1));
}

// ---------------------------------------------------------------------------
__global__ void k_pack(const float* __restrict__ f) {
    size_t i = ((size_t)blockIdx.x * 256 + threadIdx.x) * 4;
    float4 v = *(const float4*)(f + i);
    uint4 wv = make_uint4(pack_hl(v.x), pack_hl(v.y), pack_hl(v.z), pack_hl(v.w));
    *(uint4*)&g_fw[i] = wv;
}

// l2-normalize bases over C, broadcast to batches, store packed words
__global__ void k_init(const float* __restrict__ bases) {
    int k = blockIdx.x, tid = threadIdx.x;
    float s = 0.f;
    for (int c = tid; c < Cn; c += 128) {
        float v = bases[c * Kn + k];
        s += v * v;
    }
    __shared__ float sh[128];
    sh[tid] = s;
    __syncthreads();
    for (int o = 64; o > 0; o >>= 1) {
        if (tid < o) sh[tid] += sh[tid + o];
        __syncthreads();
    }
    float inv = 1.f / (EPSF + sqrtf(sh[0]));
    for (int c = tid; c < Cn; c += 128) {
        u32 wv = pack_hl(bases[c * Kn + k] * inv);
        for (int b = 0; b < Bn; b++) g_bw[(b * Cn + c) * Kn + k] = wv;
    }
}

__global__ void k_zero_cs() {
    int i = threadIdx.x;
    if (i < Bn * Kn) g_colsum[i] = 0.f;
}

// ---------------------------------------------------------------------------
// att[n,k] = softmax_k( sum_c f[c,n]*b[c,k] ); packed words out + colsum.
// grid (Nn/256, Bn), 256 thr (8 warps); warp = 32n x 64k; 32-c chunks.
__global__ __launch_bounds__(256, 2) void k_att() {
    int b = blockIdx.y, n0 = blockIdx.x * 256;
    int tid = threadIdx.x, lane = tid & 31, w = tid >> 5;
    int q = lane & 3, g = lane >> 2;

    __shared__ u32 sA[32][264];   // [c-word][n], pad 8
    __shared__ u32 sB[32][72];    // [c-word][k]
    __shared__ float colsh[Kn];

    float acc[2][8][4];
#pragma unroll
    for (int mt = 0; mt < 2; mt++)
#pragma unroll
        for (int j = 0; j < 8; j++)
#pragma unroll
            for (int i = 0; i < 4; i++) acc[mt][j][i] = 0.f;

    const u32* fw = g_fw + (size_t)b * Cn * Nn;
    const u32* bw = g_bw + (size_t)b * Cn * Kn;

    for (int c0 = 0; c0 < Cn; c0 += 32) {
#pragma unroll
        for (int t = 0; t < 8; t++) {      // stage A: 32 c-words x 256 n
            int idx = tid + t * 256;       // 0..2047
            int c = idx >> 6, nq = idx & 63;
            *(uint4*)&sA[c][nq * 4] =
                *(const uint4*)&fw[(size_t)(c0 + c) * Nn + n0 + nq * 4];
        }
#pragma unroll
        for (int t = 0; t < 2; t++) {      // stage B: 32 c-words x 64 k
            int idx = tid + t * 256;       // 0..511
            int c = idx >> 4, kq = idx & 15;
            *(uint4*)&sB[c][kq * 4] = *(const uint4*)&bw[(c0 + c) * Kn + kq * 4];
        }
        __syncthreads();
#pragma unroll
        for (int ch = 0; ch < 4; ch++) {
            u32 a[2][4];
#pragma unroll
            for (int mt = 0; mt < 2; mt++) {
                int m = 32 * w + 16 * mt + g;
                a[mt][0] = sA[8 * ch + q][m];
                a[mt][1] = sA[8 * ch + q][m + 8];
                a[mt][2] = sA[8 * ch + q + 4][m];
                a[mt][3] = sA[8 * ch + q + 4][m + 8];
            }
#pragma unroll
            for (int fj = 0; fj < 8; fj++) {
                u32 b0 = sB[8 * ch + q][8 * fj + g];
                u32 b1 = sB[8 * ch + q + 4][8 * fj + g];
                u32 b0s = swap16(b0), b1s = swap16(b1);
                mma_bf16(acc[0][fj], a[0], b0, b1);
                mma_bf16(acc[0][fj], a[0], b0s, b1s);
                mma_bf16(acc[1][fj], a[1], b0, b1);
                mma_bf16(acc[1][fj], a[1], b0s, b1s);
            }
        }
        __syncthreads();
    }

    if (tid < Kn) colsh[tid] = 0.f;

    u32* attb = g_attw + (size_t)b * Nn * Kn;
    float cacc0[8], cacc1[8];
#pragma unroll
    for (int fj = 0; fj < 8; fj++) { cacc0[fj] = 0.f; cacc1[fj] = 0.f; }

#pragma unroll
    for (int mt = 0; mt < 2; mt++) {
        float m0 = -1e30f, m1 = -1e30f;
#pragma unroll
        for (int fj = 0; fj < 8; fj++) {
            m0 = fmaxf(m0, fmaxf(acc[mt][fj][0], acc[mt][fj][1]));
            m1 = fmaxf(m1, fmaxf(acc[mt][fj][2], acc[mt][fj][3]));
        }
        m0 = fmaxf(m0, __shfl_xor_sync(0xffffffffu, m0, 1));
        m0 = fmaxf(m0, __shfl_xor_sync(0xffffffffu, m0, 2));
        m1 = fmaxf(m1, __shfl_xor_sync(0xffffffffu, m1, 1));
        m1 = fmaxf(m1, __shfl_xor_sync(0xffffffffu, m1, 2));
        float s0 = 0.f, s1 = 0.f;
#pragma unroll
        for (int fj = 0; fj < 8; fj++) {
            acc[mt][fj][0] = __expf(acc[mt][fj][0] - m0);
            acc[mt][fj][1] = __expf(acc[mt][fj][1] - m0);
            acc[mt][fj][2] = __expf(acc[mt][fj][2] - m1);
            acc[mt][fj][3] = __expf(acc[mt][fj][3] - m1);
            s0 += acc[mt][fj][0] + acc[mt][fj][1];
            s1 += acc[mt][fj][2] + acc[mt][fj][3];
        }
        s0 += __shfl_xor_sync(0xffffffffu, s0, 1);
        s0 += __shfl_xor_sync(0xffffffffu, s0, 2);
        s1 += __shfl_xor_sync(0xffffffffu, s1, 1);
        s1 += __shfl_xor_sync(0xffffffffu, s1, 2);
        float i0 = 1.f / s0, i1 = 1.f / s1;

        int r = n0 + 32 * w + 16 * mt + g;
#pragma unroll
        for (int fj = 0; fj < 8; fj++) {
            float v0 = acc[mt][fj][0] * i0, v1 = acc[mt][fj][1] * i0;
            float v2 = acc[mt][fj][2] * i1, v3 = acc[mt][fj][3] * i1;
            int k0 = 8 * fj + 2 * q;
            *(uint2*)&attb[(size_t)r * Kn + k0] = make_uint2(pack_hl(v0), pack_hl(v1));
            *(uint2*)&attb[(size_t)(r + 8) * Kn + k0] = make_uint2(pack_hl(v2), pack_hl(v3));
            cacc0[fj] += v0 + v2;
            cacc1[fj] += v1 + v3;
        }
    }
    __syncthreads();   // colsh zeroed
#pragma unroll
    for (int fj = 0; fj < 8; fj++) {
#pragma unroll
        for (int s = 4; s < 32; s <<= 1) {
            cacc0[fj] += __shfl_xor_sync(0xffffffffu, cacc0[fj], s);
            cacc1[fj] += __shfl_xor_sync(0xffffffffu, cacc1[fj], s);
        }
        if (lane < 4) {
            atomicAdd(&colsh[8 * fj + 2 * q], cacc0[fj]);
            atomicAdd(&colsh[8 * fj + 2 * q + 1], cacc1[fj]);
        }
    }
    __syncthreads();
    if (tid < Kn) atomicAdd(&g_colsum[b * Kn + tid], colsh[tid]);
}

// ---------------------------------------------------------------------------
// part[c,k] = sum_{n in chunk} f[c,n]*att[n,k]
// grid (Cn/256, NCHUNK, Bn), 256 thr; warp = 32c x 64k; 32-n chunks.
__global__ __launch_bounds__(256, 2) void k_bnew() {
    int b = blockIdx.z, chunk = blockIdx.y, ct = blockIdx.x * 256;
    int tid = threadIdx.x, lane = tid & 31, w = tid >> 5;
    int q = lane & 3, g = lane >> 2;

    __shared__ u32 sA[256][36];   // [c][n-word]
    __shared__ u32 sB[32][72];    // [n-word][k]

    float acc[2][8][4];
#pragma unroll
    for (int mt = 0; mt < 2; mt++)
#pragma unroll
        for (int j = 0; j < 8; j++)
#pragma unroll
            for (int i = 0; i < 4; i++) acc[mt][j][i] = 0.f;

    const u32* fw = g_fw + (size_t)b * Cn * Nn + (size_t)ct * Nn;
    const u32* aw = g_attw + (size_t)b * Nn * Kn;
    int nb0 = chunk * (Nn / NCHUNK), nb1 = nb0 + Nn / NCHUNK;

    for (int nb = nb0; nb < nb1; nb += 32) {
#pragma unroll
        for (int t = 0; t < 8; t++) {      // stage A: 256 c x 32 n-words
            int idx = tid + t * 256;
            int c = idx >> 3, nq = idx & 7;
            *(uint4*)&sA[c][nq * 4] = *(const uint4*)&fw[(size_t)c * Nn + nb + nq * 4];
        }
#pragma unroll
        for (int t = 0; t < 2; t++) {      // stage B: 32 n-words x 64 k
            int idx = tid + t * 256;
            int nn = idx >> 4, kq = idx & 15;
            *(uint4*)&sB[nn][kq * 4] =
                *(const uint4*)&aw[(size_t)(nb + nn) * Kn + kq * 4];
        }
        __syncthreads();
#pragma unroll
        for (int ch = 0; ch < 4; ch++) {
            u32 a[2][4];
#pragma unroll
            for (int mt = 0; mt < 2; mt++) {
                int m = 32 * w + 16 * mt + g;
                a[mt][0] = sA[m][8 * ch + q];
                a[mt][1] = sA[m + 8][8 * ch + q];
                a[mt][2] = sA[m][8 * ch + q + 4];
                a[mt][3] = sA[m + 8][8 * ch + q + 4];
            }
#pragma unroll
            for (int fj = 0; fj < 8; fj++) {
                u32 b0 = sB[8 * ch + q][8 * fj + g];
                u32 b1 = sB[8 * ch + q + 4][8 * fj + g];
                u32 b0s = swap16(b0), b1s = swap16(b1);
                mma_bf16(acc[0][fj], a[0], b0, b1);
                mma_bf16(acc[0][fj], a[0], b0s, b1s);
                mma_bf16(acc[1][fj], a[1], b0, b1);
                mma_bf16(acc[1][fj], a[1], b0s, b1s);
            }
        }
        __syncthreads();
    }

    float* pb = g_part[chunk] + (size_t)(b * Cn + ct) * Kn;
#pragma unroll
    for (int mt = 0; mt < 2; mt++) {
        int c = 32 * w + 16 * mt + g;
#pragma unroll
        for (int fj = 0; fj < 8; fj++) {
            int k0 = 8 * fj + 2 * q;
            *(float2*)&pb[(size_t)c * Kn + k0] =
                make_float2(acc[mt][fj][0], acc[mt][fj][1]);
            *(float2*)&pb[(size_t)(c + 8) * Kn + k0] =
                make_float2(acc[mt][fj][2], acc[mt][fj][3]);
        }
    }
}

// ---------------------------------------------------------------------------
__global__ void k_sum() {
    int i = blockIdx.x * 256 + threadIdx.x;
    float s = 0.f;
#pragma unroll
    for (int ch = 0; ch < NCHUNK; ch++) s += g_part[ch][i];
    g_bnew[i] = s;
}

// fused l1(via colsum)+l2 norm; writes packed base words; rezeroes colsum
__global__ void k_bnorm() {
    int blk = blockIdx.x, b = blk >> 6, k = blk & 63, tid = threadIdx.x;
    const float* src = g_bnew + (b * Cn) * Kn + k;
    float v[4], s = 0.f;
#pragma unroll
    for (int i = 0; i < 4; i++) {
        v[i] = src[(tid + i * 128) * Kn];
        s += v[i] * v[i];
    }
    __shared__ float sh[128];
    sh[tid] = s;
    __syncthreads();
    for (int o = 64; o > 0; o >>= 1) {
        if (tid < o) sh[tid] += sh[tid + o];
        __syncthreads();
    }
    float cs = g_colsum[b * Kn + k];
    float inv = 1.f / ((EPSF + cs) * EPSF + sqrtf(sh[0]));
    u32* dst = g_bw + (b * Cn) * Kn + k;
#pragma unroll
    for (int i = 0; i < 4; i++) dst[(tid + i * 128) * Kn] = pack_hl(v[i] * inv);
    __syncthreads();
    if (tid == 0) g_colsum[b * Kn + k] = 0.f;   // ready for next stage
}

// ---------------------------------------------------------------------------
// out[c,n] = sum_k b[c,k]*att[n,k]; A = b words (SMEM), B = attw tiles with
// TRANSPOSED fragment indexing (banks (36g+q)%32 = 4g+q, conflict-free) —
// no transposed attention copy needed.
// grid (Nn/64, Cn/128, Bn), 256 thr; warp = 16c x 64n.
__global__ __launch_bounds__(256) void k_recon(float* __restrict__ out) {
    int b = blockIdx.z, ct = blockIdx.y * 128, n0 = blockIdx.x * 64;
    int tid = threadIdx.x, lane = tid & 31, w = tid >> 5;
    int q = lane & 3, g = lane >> 2;

    __shared__ u32 sA[128][68];   // [c][k-word]
    __shared__ u32 sT[64][36];    // [n][k-word half], pad 4

    const u32* bw = g_bw + (size_t)(b * Cn + ct) * Kn;
#pragma unroll
    for (int t = 0; t < 8; t++) {
        int idx = tid + t * 256;
        int c = idx >> 4, kq = idx & 15;
        *(uint4*)&sA[c][kq * 4] = *(const uint4*)&bw[(size_t)c * Kn + kq * 4];
    }

    const u32* aw = g_attw + ((size_t)b * Nn + n0) * Kn;
    float acc[8][4];
#pragma unroll
    for (int j = 0; j < 8; j++)
#pragma unroll
        for (int i = 0; i < 4; i++) acc[j][i] = 0.f;

#pragma unroll
    for (int half = 0; half < 2; half++) {
        __syncthreads();
#pragma unroll
        for (int t = 0; t < 2; t++) {      // stage: 64 n x 32 k-words (8KB)
            int idx = tid + t * 256;       // 0..511
            int n = idx >> 3, kq = idx & 7;
            *(uint4*)&sT[n][kq * 4] =
                *(const uint4*)&aw[(size_t)n * Kn + 32 * half + kq * 4];
        }
        __syncthreads();
#pragma unroll
        for (int chl = 0; chl < 4; chl++) {
            int colb = 32 * half + 8 * chl;
            u32 a[4];
            a[0] = sA[16 * w + g][colb + q];
            a[1] = sA[16 * w + g + 8][colb + q];
            a[2] = sA[16 * w + g][colb + q + 4];
            a[3] = sA[16 * w + g + 8][colb + q + 4];
#pragma unroll
            for (int fj = 0; fj < 8; fj++) {
                u32 b0 = sT[8 * fj + g][8 * chl + q];
                u32 b1 = sT[8 * fj + g][8 * chl + q + 4];
                mma_bf16(acc[fj], a, b0, b1);
                mma_bf16(acc[fj], a, swap16(b0), swap16(b1));
            }
        }
    }

    float* ob = out + (size_t)(b * Cn + ct) * Nn + n0;
    int c = 16 * w + g;
#pragma unroll
    for (int fj = 0; fj < 8; fj++) {
        int n = 8 * fj + 2 * q;
        *(float2*)&ob[(size_t)c * Nn + n] = make_float2(acc[fj][0], acc[fj][1]);
        *(float2*)&ob[(size_t)(c + 8) * Nn + n] = make_float2(acc[fj][2], acc[fj][3]);
    }
}

// ---------------------------------------------------------------------------
extern "C" void kernel_launch(void* const* d_in, const int* in_sizes, int n_in,
                              void* d_out, int out_size) {
    const float* feats = (const float*)d_in[0];
    const float* bases = (const float*)d_in[1];
    float* out = (float*)d_out;
    (void)in_sizes; (void)n_in; (void)out_size;

    k_pack<<<(int)(((size_t)Bn * Cn * Nn / 4) / 256), 256>>>(feats);
    k_init<<<Kn, 128>>>(bases);
    k_zero_cs<<<1, 1024>>>();

    for (int s = 0; s < NUM_STAGES; s++) {
        k_att<<<dim3(Nn / 256, Bn), 256>>>();
        k_bnew<<<dim3(Cn / 256, NCHUNK, Bn), 256>>>();
        k_sum<<<PSZ / 256, 256>>>();
        k_bnorm<<<Bn * Kn, 128>>>();
    }
    k_recon<<<dim3(Nn / 64, Cn / 128, Bn), 256>>>(out);
}